// round 5
// baseline (speedup 1.0000x reference)
#include <cuda_runtime.h>
#include <math.h>

#define HH 512
#define WW 512
#define BN 32
#define CN 3
#define HW (HH * WW)

// Scratch (allocation-free rule: __device__ globals)
__device__ float g_Minv[BN * 9];
__device__ float g_A[HW];          // L * 0.85
__device__ float g_Z[CN * HW];     // min(z1,z2) * 0.15

// ---------------------------------------------------------------------------
// Closed-form homography (Heckbert square->quad) + 3x3 inverse, fp64.
// ---------------------------------------------------------------------------
__device__ __forceinline__ void solve_one(int b, const float* __restrict__ dst_off) {
    const double bu[4] = {0.0, 512.0, 512.0, 0.0};
    const double bv[4] = {0.0, 0.0, 512.0, 512.0};
    double u[4], v[4];
    #pragma unroll
    for (int i = 0; i < 4; i++) {
        u[i] = bu[i] + (double)dst_off[(b * 4 + i) * 2 + 0];
        v[i] = bv[i] + (double)dst_off[(b * 4 + i) * 2 + 1];
    }
    double sx  = u[0] - u[1] + u[2] - u[3];
    double sy  = v[0] - v[1] + v[2] - v[3];
    double dx1 = u[1] - u[2], dx2 = u[3] - u[2];
    double dy1 = v[1] - v[2], dy2 = v[3] - v[2];
    double den = dx1 * dy2 - dx2 * dy1;
    double g = (sx * dy2 - dx2 * sy) / den;
    double h = (dx1 * sy - sx * dy1) / den;
    double a = u[1] - u[0] + g * u[1];
    double bb = u[3] - u[0] + h * u[3];
    double c = u[0];
    double d = v[1] - v[0] + g * v[1];
    double e = v[3] - v[0] + h * v[3];
    double f = v[0];
    const double is = 1.0 / 511.0;
    double m[9] = {a * is, bb * is, c,
                   d * is, e  * is, f,
                   g * is, h  * is, 1.0};

    double det = m[0] * (m[4] * m[8] - m[5] * m[7])
               - m[1] * (m[3] * m[8] - m[5] * m[6])
               + m[2] * (m[3] * m[7] - m[4] * m[6]);
    double id = 1.0 / det;

    float* o = g_Minv + b * 9;
    o[0] = (float)( (m[4] * m[8] - m[5] * m[7]) * id);
    o[1] = (float)(-(m[1] * m[8] - m[2] * m[7]) * id);
    o[2] = (float)( (m[1] * m[5] - m[2] * m[4]) * id);
    o[3] = (float)(-(m[3] * m[8] - m[5] * m[6]) * id);
    o[4] = (float)( (m[0] * m[8] - m[2] * m[6]) * id);
    o[5] = (float)(-(m[0] * m[5] - m[2] * m[3]) * id);
    o[6] = (float)( (m[3] * m[7] - m[4] * m[6]) * id);
    o[7] = (float)(-(m[0] * m[7] - m[1] * m[6]) * id);
    o[8] = (float)( (m[0] * m[4] - m[1] * m[3]) * id);
}

// ---------------------------------------------------------------------------
// Fused setup: light mask (x0.85) + moire (x0.15) + per-batch homographies.
// All trig via MUFU fast paths with explicit period-1 reduction.
// ---------------------------------------------------------------------------
__global__ void setup_kernel(const float* __restrict__ dst_off,
                             const float* __restrict__ ab,
                             const float* __restrict__ centers,
                             const int* __restrict__ cflag,
                             const int* __restrict__ direction,
                             const int* __restrict__ light_xy,
                             const int* __restrict__ theta) {
    if (blockIdx.x == gridDim.x - 1) {
        int b = threadIdx.x;
        if (b < BN) solve_one(b, dst_off);
        return;
    }
    int idx = blockIdx.x * blockDim.x + threadIdx.x;
    int i = idx / WW;   // row
    int j = idx % WW;   // col

    float a = ab[0], bb = ab[1];
    float L;
    if (cflag[0] == 0) {
        int k = direction[0] - 1;  // rot90 count {0,1,2,3}
        int t = (k == 0) ? i : (k == 1) ? j : (k == 2) ? (HH - 1 - i) : (WW - 1 - j);
        L = -((bb - a) / (float)(HH - 1)) * ((float)t - (float)WW) + a;
    } else {
        float x = (float)light_xy[0], y = (float)light_xy[1];
        float d0 = sqrtf(x * x + y * y);
        float d1 = sqrtf((x - 255.f) * (x - 255.f) + y * y);
        float d2 = sqrtf(x * x + (y - 255.f) * (y - 255.f));
        float d3 = sqrtf((x - 512.f) * (x - 512.f) + (y - 512.f) * (y - 512.f));
        float ml = fmaxf(fmaxf(d0, d1), fmaxf(d2, d3));
        float dx = (float)i - x, dy = (float)j - y;
        float dist = sqrtf(dx * dx + dy * dy);
        L = dist / ml * (a - bb) + bb;
    }
    g_A[idx] = L * 0.85f;

    const float TWO_PI = 6.283185307179586f;
    float xg = (float)(i + 1), yg = (float)(j + 1);
    #pragma unroll
    for (int k = 0; k < 3; k++) {
        float cx = centers[k * 2 + 0], cy = centers[k * 2 + 1];
        float th = (float)theta[k] * 0.017453292519943295f;
        float cth = __cosf(th), sth = __sinf(th);     // MUFU, th in [0, pi)
        float dx = xg - cx, dy = yg - cy;
        float dist = sqrtf(dx * dx + dy * dy);
        float f1 = dist - floorf(dist);               // period-1 reduction
        float t2 = cth * xg + sth * yg;
        float f2 = t2 - floorf(t2);
        float z1 = 0.5f + 0.5f * __cosf(TWO_PI * f1);
        float z2 = 0.5f + 0.5f * __cosf(TWO_PI * f2);
        g_Z[k * HW + idx] = fminf(z1, z2) * 0.15f;
    }
}

// ---------------------------------------------------------------------------
// Fused warp + blend. Block = 512 threads = one (b, y) output row.
// Phase 1: thread t -> pixel x=t. 12 predicated gathers with raw (unclamped)
//          indices: i00 = iy*512+ix, siblings at immediate offsets
//          +4 / +2048 / +2052 bytes. Predicated-off LDG never dereferences.
// Phase 2: threads 0..383: ch = t>>7, x0 = (t&127)*4 -> float4 blend.
// ---------------------------------------------------------------------------
__global__ void __launch_bounds__(512) main_kernel(const float* __restrict__ img,
                                                   const float* __restrict__ noise,
                                                   float* __restrict__ out) {
    __shared__ float sres[3][WW];

    int b = blockIdx.y;
    int y = blockIdx.x;
    int tid = threadIdx.x;

    const float* Mi = g_Minv + b * 9;
    float m00 = Mi[0], m01 = Mi[1], m02 = Mi[2];
    float m10 = Mi[3], m11 = Mi[4], m12 = Mi[5];
    float m20 = Mi[6], m21 = Mi[7], m22 = Mi[8];
    float fy = (float)y;
    float c0 = m01 * fy + m02;
    float c1 = m11 * fy + m12;
    float c2 = m21 * fy + m22;

    {
        float fx = (float)tid;
        float inv = 1.0f / (m20 * fx + c2);
        float xs = (m00 * fx + c0) * inv;
        float ys = (m10 * fx + c1) * inv;
        float xf = floorf(xs), yf = floorf(ys);
        float wx = xs - xf, wy = ys - yf;
        int ix = (int)xf, iy = (int)yf;
        bool vx0 = ((unsigned)ix < WW);
        bool vx1 = ((unsigned)(ix + 1) < WW);
        bool vy0 = ((unsigned)iy < HH);
        bool vy1 = ((unsigned)(iy + 1) < HH);
        bool p00 = vx0 && vy0, p01 = vx1 && vy0;
        bool p10 = vx0 && vy1, p11 = vx1 && vy1;
        float w00 = (1.f - wx) * (1.f - wy);
        float w01 = wx * (1.f - wy);
        float w10 = (1.f - wx) * wy;
        float w11 = wx * wy;
        int i00 = iy * WW + ix;   // raw; only dereferenced when predicate true

        const float* base = img + (size_t)b * (3 * HW);
        #pragma unroll
        for (int ch = 0; ch < 3; ch++) {
            const float* p = base + ch * HW + i00;
            float v00 = p00 ? __ldg(p)          : 0.f;
            float v01 = p01 ? __ldg(p + 1)      : 0.f;
            float v10 = p10 ? __ldg(p + WW)     : 0.f;
            float v11 = p11 ? __ldg(p + WW + 1) : 0.f;
            sres[ch][tid] = v00 * w00 + v01 * w01 + v10 * w10 + v11 * w11;
        }
    }

    __syncthreads();

    // Phase 2: 384 threads, each blends one float4 of one channel.
    if (tid < 384) {
        const float kn = 0.031622776601683794f;  // sqrt(0.001)
        int ch = tid >> 7;
        int x0 = (tid & 127) * 4;
        float4 av = *(const float4*)(g_A + (size_t)y * WW + x0);
        size_t off = ((size_t)(b * 3 + ch) * HH + y) * WW + x0;
        float4 nv = __ldcs((const float4*)(noise + off));
        float4 zv = *(const float4*)(g_Z + ((size_t)ch * HH + y) * WW + x0);
        float4 rv = *(const float4*)(&sres[ch][x0]);
        float4 ov;
        ov.x = rv.x * av.x + zv.x + kn * nv.x;
        ov.y = rv.y * av.y + zv.y + kn * nv.y;
        ov.z = rv.z * av.z + zv.z + kn * nv.z;
        ov.w = rv.w * av.w + zv.w + kn * nv.w;
        __stcs((float4*)(out + off), ov);
    }
}

// ---------------------------------------------------------------------------
extern "C" void kernel_launch(void* const* d_in, const int* in_sizes, int n_in,
                              void* d_out, int out_size) {
    const float* image    = (const float*)d_in[0];
    const float* dst_off  = (const float*)d_in[1];
    const float* ab       = (const float*)d_in[2];
    const float* centers  = (const float*)d_in[3];
    const float* noise    = (const float*)d_in[4];
    const int*   c        = (const int*)d_in[5];
    const int*   direction= (const int*)d_in[6];
    const int*   light_xy = (const int*)d_in[7];
    const int*   theta    = (const int*)d_in[8];
    float* out = (float*)d_out;

    setup_kernel<<<HW / 256 + 1, 256>>>(dst_off, ab, centers, c,
                                        direction, light_xy, theta);
    dim3 grid(HH, BN);
    main_kernel<<<grid, 512>>>(image, noise, out);
}